// round 1
// baseline (speedup 1.0000x reference)
#include <cuda_runtime.h>

// Problem constants
#define DM 1024      // d_model
#define NH 16        // n_heads
#define DH 64        // d_head
#define BB 4         // batch
#define SS 2048      // seq len
#define MR (BB*SS)   // 8192 rows

// ---------------------------------------------------------------------------
// Scratch (static device globals; no runtime allocation allowed)
// q,k,v stored [b][h][s][d]; z stored [b][s][h][d] (== [8192][1024] row-major)
// ---------------------------------------------------------------------------
static __device__ float g_q[(size_t)BB * NH * SS * DH];
static __device__ float g_k[(size_t)BB * NH * SS * DH];
static __device__ float g_v[(size_t)BB * NH * SS * DH];
static __device__ float g_z[(size_t)BB * SS * NH * DH];

// ---------------------------------------------------------------------------
// Packed fp32x2 FMA / MUL (Blackwell sm_103a): 2 FMAs per issue slot.
// ---------------------------------------------------------------------------
__device__ __forceinline__ void ffma2(float2 &c, const float2 a, const float2 b) {
    asm("{\n\t"
        ".reg .b64 ra, rb, rc;\n\t"
        "mov.b64 ra, {%2, %3};\n\t"
        "mov.b64 rb, {%4, %5};\n\t"
        "mov.b64 rc, {%0, %1};\n\t"
        "fma.rn.f32x2 rc, ra, rb, rc;\n\t"
        "mov.b64 {%0, %1}, rc;\n\t"
        "}"
        : "+f"(c.x), "+f"(c.y)
        : "f"(a.x), "f"(a.y), "f"(b.x), "f"(b.y));
}

__device__ __forceinline__ void fmul2(float2 &c, const float2 a) {
    asm("{\n\t"
        ".reg .b64 ra, rc;\n\t"
        "mov.b64 ra, {%2, %3};\n\t"
        "mov.b64 rc, {%0, %1};\n\t"
        "mul.rn.f32x2 rc, rc, ra;\n\t"
        "mov.b64 {%0, %1}, rc;\n\t"
        "}"
        : "+f"(c.x), "+f"(c.y)
        : "f"(a.x), "f"(a.y));
}

// ---------------------------------------------------------------------------
// Kernel 1: fused QKV projection.
// GEMM: X[8192,1024] @ Wcat[1024, 3072] where columns 0..1023 -> Q, etc.
// Output scattered into g_q/g_k/g_v in [b][h][s][d] layout, + bias.
// Tiling: BM=128, BN=128, BK=16, 256 threads, 8x8 micro-tile per thread.
// ---------------------------------------------------------------------------
__global__ void __launch_bounds__(256) qkv_gemm_kernel(
    const float* __restrict__ X,
    const float* __restrict__ Wq, const float* __restrict__ Wk,
    const float* __restrict__ Wv,
    const float* __restrict__ bQ, const float* __restrict__ bK,
    const float* __restrict__ bV)
{
    __shared__ float As[16][128];   // [k][m]
    __shared__ float Bs[16][128];   // [k][n]

    const int tid = threadIdx.x;
    const int tx  = tid & 15;       // N direction (8 cols each)
    const int ty  = tid >> 4;       // M direction (8 rows each)
    const int m0  = blockIdx.y * 128;
    const int n0  = blockIdx.x * 128;     // global col in [0,3072)
    const int sel = n0 >> 10;              // 0=Q, 1=K, 2=V (tiles never straddle)
    const int nb  = n0 & 1023;             // section-local col base

    const float* W    = (sel == 0) ? Wq : (sel == 1) ? Wk : Wv;
    const float* bias = (sel == 0) ? bQ : (sel == 1) ? bK : bV;
    float*       dst  = (sel == 0) ? g_q : (sel == 1) ? g_k : g_v;

    // Cooperative load indices
    const int arow = tid >> 1;            // 0..127
    const int acol = (tid & 1) * 8;       // 0 or 8 (k-offset)
    const int brow = tid >> 4;            // 0..15  (k-row)
    const int bcol = (tid & 15) * 8;      // 0..120

    const int cb = nb + bcol;             // section-local column of B load
    const int h0 = cb >> 6;
    const int d0 = cb & 63;                // 8-run stays inside one head

    const float* ax = X + (size_t)(m0 + arow) * DM + acol;
    // W_{sel}[h][m][d]: advance m by k
    const float* bx = W + (size_t)h0 * (DM * DH) + (size_t)brow * DH + d0;

    float2 c2[8][4];
#pragma unroll
    for (int i = 0; i < 8; i++)
#pragma unroll
        for (int j = 0; j < 4; j++) c2[i][j] = make_float2(0.f, 0.f);

    for (int k0 = 0; k0 < DM; k0 += 16) {
        float4 av0 = *(const float4*)(ax + k0);
        float4 av1 = *(const float4*)(ax + k0 + 4);
        float4 bv0 = *(const float4*)(bx + (size_t)k0 * DH);
        float4 bv1 = *(const float4*)(bx + (size_t)k0 * DH + 4);
        __syncthreads();   // previous tile's compute done before overwrite
        As[acol + 0][arow] = av0.x;
        As[acol + 1][arow] = av0.y;
        As[acol + 2][arow] = av0.z;
        As[acol + 3][arow] = av0.w;
        As[acol + 4][arow] = av1.x;
        As[acol + 5][arow] = av1.y;
        As[acol + 6][arow] = av1.z;
        As[acol + 7][arow] = av1.w;
        *(float4*)&Bs[brow][bcol]     = bv0;
        *(float4*)&Bs[brow][bcol + 4] = bv1;
        __syncthreads();
#pragma unroll
        for (int kk = 0; kk < 16; kk++) {
            float4 a0 = *(const float4*)&As[kk][ty * 8];
            float4 a1 = *(const float4*)&As[kk][ty * 8 + 4];
            float4 b0 = *(const float4*)&Bs[kk][tx * 8];
            float4 b1 = *(const float4*)&Bs[kk][tx * 8 + 4];
            float  af[8] = {a0.x, a0.y, a0.z, a0.w, a1.x, a1.y, a1.z, a1.w};
            float2 bf[4] = {make_float2(b0.x, b0.y), make_float2(b0.z, b0.w),
                            make_float2(b1.x, b1.y), make_float2(b1.z, b1.w)};
#pragma unroll
            for (int i = 0; i < 8; i++) {
                float2 aa = make_float2(af[i], af[i]);
#pragma unroll
                for (int j = 0; j < 4; j++) ffma2(c2[i][j], aa, bf[j]);
            }
        }
    }

    // Epilogue: bias + scatter to [b][h][s][d]
    const int ch = (nb + tx * 8) >> 6;
    const int cd = (nb + tx * 8) & 63;
#pragma unroll
    for (int i = 0; i < 8; i++) {
        int r = m0 + ty * 8 + i;
        int b = r >> 11;           // /2048
        int s = r & (SS - 1);
        float* orow = dst + ((size_t)(b * NH + ch) * SS + s) * DH + cd;
#pragma unroll
        for (int j = 0; j < 4; j++) {
            float2 v = c2[i][j];
            v.x += bias[ch * DH + cd + 2 * j];
            v.y += bias[ch * DH + cd + 2 * j + 1];
            *(float2*)(orow + 2 * j) = v;
        }
    }
}

// ---------------------------------------------------------------------------
// Kernel 2: causal flash attention, fp32.
// One block = (b,h) x 128 q-rows; one thread = one q-row (q[64], o[64] in regs).
// K/V tiles of 32 rows in smem; scores cached in smem for the 2-pass
// per-tile online softmax (single rescale per tile).
// ---------------------------------------------------------------------------
__global__ void __launch_bounds__(128) attn_kernel()
{
    __shared__ float sK[32][64];
    __shared__ float sV[32][64];
    __shared__ float sS[128][33];   // padded: stride 33 avoids bank conflicts

    const int tid = threadIdx.x;
    const int bh  = blockIdx.y;                       // b*16 + h
    const int qb  = (int)gridDim.x - 1 - (int)blockIdx.x;  // big tiles first
    const int row = qb * 128 + tid;

    const float* Q = g_q + (size_t)bh * SS * DH;
    const float* K = g_k + (size_t)bh * SS * DH;
    const float* V = g_v + (size_t)bh * SS * DH;

    float2 q2[32];
    {
        const float4* qrow = (const float4*)(Q + (size_t)row * DH);
#pragma unroll
        for (int i = 0; i < 16; i++) {
            float4 t = qrow[i];
            q2[2 * i]     = make_float2(t.x, t.y);
            q2[2 * i + 1] = make_float2(t.z, t.w);
        }
    }
    float2 o2[32];
#pragma unroll
    for (int i = 0; i < 32; i++) o2[i] = make_float2(0.f, 0.f);
    float m = __int_as_float(0xff800000);  // -inf
    float l = 0.f;

    const int ntiles = qb * 4 + 4;   // ceil((qb*128+128)/32)
    for (int t = 0; t < ntiles; t++) {
        const int j0 = t * 32;
        // Cooperative K/V tile loads: 512 float4 each, 4 per thread
#pragma unroll
        for (int i = 0; i < 4; i++) {
            int l4 = tid + i * 128;
            int r  = l4 >> 4;
            int c  = (l4 & 15) * 4;
            *(float4*)&sK[r][c] = *(const float4*)(K + (size_t)(j0 + r) * DH + c);
            *(float4*)&sV[r][c] = *(const float4*)(V + (size_t)(j0 + r) * DH + c);
        }
        __syncthreads();

        int jmax = row - j0 + 1;             // causal: j0+j <= row
        if (jmax > 32) jmax = 32;
        if (jmax > 0) {
            float tmax = __int_as_float(0xff800000);
            for (int j = 0; j < jmax; j++) {
                const float2* kr = (const float2*)&sK[j][0];
                float2 a0 = make_float2(0.f, 0.f), a1 = a0, a2 = a0, a3 = a0;
#pragma unroll
                for (int i = 0; i < 32; i += 4) {
                    ffma2(a0, q2[i],     kr[i]);
                    ffma2(a1, q2[i + 1], kr[i + 1]);
                    ffma2(a2, q2[i + 2], kr[i + 2]);
                    ffma2(a3, q2[i + 3], kr[i + 3]);
                }
                float s = ((a0.x + a0.y) + (a1.x + a1.y)) +
                          ((a2.x + a2.y) + (a3.x + a3.y));
                s *= 0.125f;                 // 1/sqrt(64)
                sS[tid][j] = s;
                tmax = fmaxf(tmax, s);
            }
            float mnew = fmaxf(m, tmax);
            float corr = __expf(m - mnew);   // 0 on first tile (m=-inf)
            m = mnew;
            l *= corr;
            float2 cc = make_float2(corr, corr);
#pragma unroll
            for (int i = 0; i < 32; i++) fmul2(o2[i], cc);
            for (int j = 0; j < jmax; j++) {
                float p = __expf(sS[tid][j] - m);
                l += p;
                float2 p2 = make_float2(p, p);
                const float2* vr = (const float2*)&sV[j][0];
#pragma unroll
                for (int i = 0; i < 32; i++) ffma2(o2[i], p2, vr[i]);
            }
        }
        __syncthreads();
    }

    // normalize & write z in [b][s][h][d]
    const float invl = 1.0f / l;
    const int b = bh >> 4, h = bh & 15;
    float* zrow = g_z + ((size_t)(b * SS + row) * NH + h) * DH;
#pragma unroll
    for (int i = 0; i < 16; i++) {
        float4 tvec;
        tvec.x = o2[2 * i].x * invl;
        tvec.y = o2[2 * i].y * invl;
        tvec.z = o2[2 * i + 1].x * invl;
        tvec.w = o2[2 * i + 1].y * invl;
        *(float4*)(zrow + i * 4) = tvec;
    }
}

// ---------------------------------------------------------------------------
// Kernel 3: output projection. Z[8192,1024] @ Wo'[1024,1024] + bO -> out.
// Wo is [h][d][m] contiguous == row-major [1024][1024] with row = h*64+d,
// which matches z's column layout exactly.
// ---------------------------------------------------------------------------
__global__ void __launch_bounds__(256) out_gemm_kernel(
    const float* __restrict__ Wo, const float* __restrict__ bO,
    float* __restrict__ out)
{
    __shared__ float As[16][128];
    __shared__ float Bs[16][128];

    const int tid = threadIdx.x;
    const int tx  = tid & 15;
    const int ty  = tid >> 4;
    const int m0  = blockIdx.y * 128;
    const int n0  = blockIdx.x * 128;

    const int arow = tid >> 1;
    const int acol = (tid & 1) * 8;
    const int brow = tid >> 4;
    const int bcol = (tid & 15) * 8;

    const float* ax = g_z + (size_t)(m0 + arow) * DM + acol;
    const float* bx = Wo + (size_t)brow * DM + n0 + bcol;

    float2 c2[8][4];
#pragma unroll
    for (int i = 0; i < 8; i++)
#pragma unroll
        for (int j = 0; j < 4; j++) c2[i][j] = make_float2(0.f, 0.f);

    for (int k0 = 0; k0 < DM; k0 += 16) {
        float4 av0 = *(const float4*)(ax + k0);
        float4 av1 = *(const float4*)(ax + k0 + 4);
        float4 bv0 = *(const float4*)(bx + (size_t)k0 * DM);
        float4 bv1 = *(const float4*)(bx + (size_t)k0 * DM + 4);
        __syncthreads();
        As[acol + 0][arow] = av0.x;
        As[acol + 1][arow] = av0.y;
        As[acol + 2][arow] = av0.z;
        As[acol + 3][arow] = av0.w;
        As[acol + 4][arow] = av1.x;
        As[acol + 5][arow] = av1.y;
        As[acol + 6][arow] = av1.z;
        As[acol + 7][arow] = av1.w;
        *(float4*)&Bs[brow][bcol]     = bv0;
        *(float4*)&Bs[brow][bcol + 4] = bv1;
        __syncthreads();
#pragma unroll
        for (int kk = 0; kk < 16; kk++) {
            float4 a0 = *(const float4*)&As[kk][ty * 8];
            float4 a1 = *(const float4*)&As[kk][ty * 8 + 4];
            float4 b0 = *(const float4*)&Bs[kk][tx * 8];
            float4 b1 = *(const float4*)&Bs[kk][tx * 8 + 4];
            float  af[8] = {a0.x, a0.y, a0.z, a0.w, a1.x, a1.y, a1.z, a1.w};
            float2 bf[4] = {make_float2(b0.x, b0.y), make_float2(b0.z, b0.w),
                            make_float2(b1.x, b1.y), make_float2(b1.z, b1.w)};
#pragma unroll
            for (int i = 0; i < 8; i++) {
                float2 aa = make_float2(af[i], af[i]);
#pragma unroll
                for (int j = 0; j < 4; j++) ffma2(c2[i][j], aa, bf[j]);
            }
        }
    }

    const int cbase = n0 + tx * 8;
#pragma unroll
    for (int i = 0; i < 8; i++) {
        int r = m0 + ty * 8 + i;
        float* orow = out + (size_t)r * DM + cbase;
#pragma unroll
        for (int j = 0; j < 4; j++) {
            float2 v = c2[i][j];
            v.x += bO[cbase + 2 * j];
            v.y += bO[cbase + 2 * j + 1];
            *(float2*)(orow + 2 * j) = v;
        }
    }
}

// ---------------------------------------------------------------------------
// Launch: QKV proj -> attention -> output proj (sequential on capture stream)
// ---------------------------------------------------------------------------
extern "C" void kernel_launch(void* const* d_in, const int* in_sizes, int n_in,
                              void* d_out, int out_size)
{
    (void)in_sizes; (void)n_in; (void)out_size;
    const float* resid = (const float*)d_in[0];
    const float* Wq    = (const float*)d_in[1];
    const float* Wk    = (const float*)d_in[2];
    const float* Wv    = (const float*)d_in[3];
    const float* Wo    = (const float*)d_in[4];
    const float* bq    = (const float*)d_in[5];
    const float* bk    = (const float*)d_in[6];
    const float* bv    = (const float*)d_in[7];
    const float* bo    = (const float*)d_in[8];
    float* out = (float*)d_out;

    dim3 g1(24, 64);   // 3072/128 x 8192/128
    qkv_gemm_kernel<<<g1, 256>>>(resid, Wq, Wk, Wv, bq, bk, bv);

    dim3 ga(16, 64);   // 2048/128 q-tiles x (b*h)
    attn_kernel<<<ga, 128>>>();

    dim3 g2(8, 64);    // 1024/128 x 8192/128
    out_gemm_kernel<<<g2, 256>>>(Wo, bo, out);
}

// round 3
// speedup vs baseline: 1.5453x; 1.5453x over previous
#include <cuda_runtime.h>
#include <cuda_bf16.h>
#include <cstdint>

// Problem constants
#define DM 1024      // d_model
#define NH 16        // n_heads
#define DH 64        // d_head
#define BB 4         // batch
#define SS 2048      // seq len
#define MR (BB*SS)   // 8192 rows

// ---------------------------------------------------------------------------
// Scratch (static device globals)
// ---------------------------------------------------------------------------
static __device__ float g_q[(size_t)BB * NH * SS * DH];   // [b][h][s][d]
static __device__ float g_k[(size_t)BB * NH * SS * DH];
static __device__ float g_v[(size_t)BB * NH * SS * DH];
static __device__ float g_z[(size_t)BB * SS * NH * DH];   // [b][s][h][d] == [8192][1024]

// bf16 hi/lo pairs for tensor-core 3-term split GEMMs
static __device__ __nv_bfloat16 g_xhi[(size_t)MR * DM];
static __device__ __nv_bfloat16 g_xlo[(size_t)MR * DM];
static __device__ __nv_bfloat16 g_zhi[(size_t)MR * DM];
static __device__ __nv_bfloat16 g_zlo[(size_t)MR * DM];
static __device__ __nv_bfloat16 g_wthi[(size_t)3 * DM * DM];  // [3072][1024], B[n][k]
static __device__ __nv_bfloat16 g_wtlo[(size_t)3 * DM * DM];
static __device__ __nv_bfloat16 g_wohi[(size_t)DM * DM];      // [1024][1024], B[n][k]
static __device__ __nv_bfloat16 g_wolo[(size_t)DM * DM];

// ---------------------------------------------------------------------------
// Base-arch PTX helpers (NO "a"-suffix features: this TU compiles for
// compute_103 base — tcgen05/TMEM are unavailable; mma.sync/ldmatrix/cp.async
// are sm_80+ base features and do compile)
// ---------------------------------------------------------------------------
__device__ __forceinline__ uint32_t smem_to_u32(const void* p) {
    uint32_t a;
    asm("{ .reg .u64 t; cvta.to.shared.u64 t, %1; cvt.u32.u64 %0, t; }"
        : "=r"(a) : "l"(p));
    return a;
}

#define CP_ASYNC16(saddr, gptr) \
    asm volatile("cp.async.cg.shared.global [%0], [%1], 16;" \
        :: "r"(saddr), "l"(gptr))
#define CP_COMMIT() asm volatile("cp.async.commit_group;" ::: "memory")
#define CP_WAIT(n)  asm volatile("cp.async.wait_group %0;" :: "n"(n) : "memory")

#define LDSM_X4(r, addr) \
    asm volatile("ldmatrix.sync.aligned.m8n8.x4.shared.b16 {%0,%1,%2,%3}, [%4];" \
        : "=r"((r)[0]), "=r"((r)[1]), "=r"((r)[2]), "=r"((r)[3]) : "r"(addr))

#define MMA_BF16(c, a, b) \
    asm volatile("mma.sync.aligned.m16n8k16.row.col.f32.bf16.bf16.f32 " \
        "{%0,%1,%2,%3}, {%4,%5,%6,%7}, {%8,%9}, {%0,%1,%2,%3};" \
        : "+f"((c)[0]), "+f"((c)[1]), "+f"((c)[2]), "+f"((c)[3]) \
        : "r"((a)[0]), "r"((a)[1]), "r"((a)[2]), "r"((a)[3]), \
          "r"((b)[0]), "r"((b)[1]))

// ---------------------------------------------------------------------------
// Packed fp32x2 FMA / MUL (for the fp32 attention kernel)
// ---------------------------------------------------------------------------
__device__ __forceinline__ void ffma2(float2 &c, const float2 a, const float2 b) {
    asm("{\n\t.reg .b64 ra, rb, rc;\n\t"
        "mov.b64 ra, {%2, %3};\n\t"
        "mov.b64 rb, {%4, %5};\n\t"
        "mov.b64 rc, {%0, %1};\n\t"
        "fma.rn.f32x2 rc, ra, rb, rc;\n\t"
        "mov.b64 {%0, %1}, rc;\n\t}"
        : "+f"(c.x), "+f"(c.y)
        : "f"(a.x), "f"(a.y), "f"(b.x), "f"(b.y));
}
__device__ __forceinline__ void fmul2(float2 &c, const float2 a) {
    asm("{\n\t.reg .b64 ra, rc;\n\t"
        "mov.b64 ra, {%2, %3};\n\t"
        "mov.b64 rc, {%0, %1};\n\t"
        "mul.rn.f32x2 rc, rc, ra;\n\t"
        "mov.b64 {%0, %1}, rc;\n\t}"
        : "+f"(c.x), "+f"(c.y)
        : "f"(a.x), "f"(a.y));
}

// ---------------------------------------------------------------------------
// fp32 -> bf16 hi/lo split kernels
// ---------------------------------------------------------------------------
__device__ __forceinline__ void splitbf(float x, __nv_bfloat16 &h, __nv_bfloat16 &l) {
    h = __float2bfloat16(x);
    l = __float2bfloat16(x - __bfloat162float(h));
}

__device__ __forceinline__ void split4_store(float4 v, __nv_bfloat16* hi,
                                             __nv_bfloat16* lo, size_t i4) {
    __nv_bfloat16 h0, h1, h2, h3, l0, l1, l2, l3;
    splitbf(v.x, h0, l0); splitbf(v.y, h1, l1);
    splitbf(v.z, h2, l2); splitbf(v.w, h3, l3);
    __nv_bfloat162* H = (__nv_bfloat162*)hi;
    __nv_bfloat162* L = (__nv_bfloat162*)lo;
    __nv_bfloat162 t;
    t.x = h0; t.y = h1; H[2 * i4]     = t;
    t.x = h2; t.y = h3; H[2 * i4 + 1] = t;
    t.x = l0; t.y = l1; L[2 * i4]     = t;
    t.x = l2; t.y = l3; L[2 * i4 + 1] = t;
}

__global__ void __launch_bounds__(256) split_x_kernel(const float* __restrict__ src) {
    size_t i = (size_t)blockIdx.x * 256 + threadIdx.x;   // over MR*DM/4
    float4 v = ((const float4*)src)[i];
    split4_store(v, g_xhi, g_xlo, i);
}

__global__ void __launch_bounds__(256) split_z_kernel() {
    size_t i = (size_t)blockIdx.x * 256 + threadIdx.x;
    float4 v = ((const float4*)g_z)[i];
    split4_store(v, g_zhi, g_zlo, i);
}

// W_Q/W_K/W_V [h][m][d] -> B[n][k] with n = sel*1024 + h*64 + d, k = m
__global__ void __launch_bounds__(256) conv_wqkv_kernel(
    const float* __restrict__ Wq, const float* __restrict__ Wk,
    const float* __restrict__ Wv)
{
    int idx = blockIdx.x * 256 + threadIdx.x;   // 3072*256 total
    int n  = idx % 3072;
    int kb = idx / 3072;                        // k = kb*4..+3
    int sel = n >> 10, nl = n & 1023, h = nl >> 6, d = nl & 63;
    const float* W = (sel == 0) ? Wq : (sel == 1) ? Wk : Wv;
    const float* s = W + ((size_t)h << 16) + (size_t)(kb * 4) * DH + d;
    float x0 = s[0], x1 = s[DH], x2 = s[2 * DH], x3 = s[3 * DH];
    __nv_bfloat16 h0, h1, h2, h3, l0, l1, l2, l3;
    splitbf(x0, h0, l0); splitbf(x1, h1, l1);
    splitbf(x2, h2, l2); splitbf(x3, h3, l3);
    size_t o = (size_t)n * DM + kb * 4;
    __nv_bfloat162 t;
    __nv_bfloat162* H = (__nv_bfloat162*)(g_wthi + o);
    __nv_bfloat162* L = (__nv_bfloat162*)(g_wtlo + o);
    t.x = h0; t.y = h1; H[0] = t;  t.x = h2; t.y = h3; H[1] = t;
    t.x = l0; t.y = l1; L[0] = t;  t.x = l2; t.y = l3; L[1] = t;
}

// Wo [h][d][m] == flat [1024][1024] (row = h*64+d = k) -> B[n][k] = Wo[k][n]
__global__ void __launch_bounds__(256) conv_wo_kernel(const float* __restrict__ Wo) {
    int idx = blockIdx.x * 256 + threadIdx.x;   // 1024*256 total
    int n  = idx & 1023;
    int kb = idx >> 10;
    const float* s = Wo + (size_t)(kb * 4) * DM + n;
    float x0 = s[0], x1 = s[DM], x2 = s[2 * DM], x3 = s[3 * DM];
    __nv_bfloat16 h0, h1, h2, h3, l0, l1, l2, l3;
    splitbf(x0, h0, l0); splitbf(x1, h1, l1);
    splitbf(x2, h2, l2); splitbf(x3, h3, l3);
    size_t o = (size_t)n * DM + kb * 4;
    __nv_bfloat162 t;
    __nv_bfloat162* H = (__nv_bfloat162*)(g_wohi + o);
    __nv_bfloat162* L = (__nv_bfloat162*)(g_wolo + o);
    t.x = h0; t.y = h1; H[0] = t;  t.x = h2; t.y = h3; H[1] = t;
    t.x = l0; t.y = l1; L[0] = t;  t.x = l2; t.y = l3; L[1] = t;
}

// ---------------------------------------------------------------------------
// mma.sync bf16 GEMM with 3-term split: C[m,n] = sum_k A[m,k]*B[n,k]
// CTA tile 128x128, 8 warps (4M x 2N -> warp tile 32x64), K-chunk 32,
// cp.async double-buffered. fp32 accumulate.
// mode 0: A=X(hi/lo), B=Wqkv^T; scatter to g_q/g_k/g_v + bias
// mode 1: A=Z(hi/lo), B=Wo^T; write out + bO (bias0)
// ---------------------------------------------------------------------------
#define KC 32
#define PADE 40                         // padded row length in bf16 elems
#define ROWB (PADE*2)                   // 80 bytes row stride
#define TILE_B (128*ROWB)               // 10240 bytes per tile
#define STAGE_B (4*TILE_B)              // Ah,Al,Bh,Bl = 40960
#define SMEM_DYN (2*STAGE_B)            // 81920

__device__ __forceinline__ void load_stage(uint32_t sb,
    const __nv_bfloat16* Ah, const __nv_bfloat16* Al,
    const __nv_bfloat16* Bh, const __nv_bfloat16* Bl,
    int m0, int n0, int k0, int tid)
{
#pragma unroll
    for (int i = 0; i < 2; i++) {
        int c   = tid + i * 256;        // 512 16B-chunks per tile
        int row = c >> 2;
        int ko  = (c & 3) * 8;          // k offset in elems
        uint32_t soff = (uint32_t)(row * ROWB + (c & 3) * 16);
        CP_ASYNC16(sb + 0 * TILE_B + soff, Ah + (size_t)(m0 + row) * DM + k0 + ko);
        CP_ASYNC16(sb + 1 * TILE_B + soff, Al + (size_t)(m0 + row) * DM + k0 + ko);
        CP_ASYNC16(sb + 2 * TILE_B + soff, Bh + (size_t)(n0 + row) * DM + k0 + ko);
        CP_ASYNC16(sb + 3 * TILE_B + soff, Bl + (size_t)(n0 + row) * DM + k0 + ko);
    }
}

__global__ void __launch_bounds__(256) mma_gemm_kernel(
    const float* __restrict__ bias0, const float* __restrict__ bias1,
    const float* __restrict__ bias2, float* __restrict__ outp, int mode)
{
    extern __shared__ char smem[];
    const uint32_t sb0 = smem_to_u32(smem);

    const int tid  = threadIdx.x;
    const int lane = tid & 31;
    const int wid  = tid >> 5;
    const int wm   = wid & 3;            // 4 warps in M
    const int wn   = wid >> 2;           // 2 warps in N
    const int m0   = blockIdx.y * 128;
    const int n0   = blockIdx.x * 128;

    const __nv_bfloat16* Ahi = (mode == 0) ? g_xhi  : g_zhi;
    const __nv_bfloat16* Alo = (mode == 0) ? g_xlo  : g_zlo;
    const __nv_bfloat16* Bhi = (mode == 0) ? g_wthi : g_wohi;
    const __nv_bfloat16* Blo = (mode == 0) ? g_wtlo : g_wolo;

    float c[2][8][4];
#pragma unroll
    for (int i = 0; i < 2; i++)
#pragma unroll
        for (int j = 0; j < 8; j++)
#pragma unroll
            for (int q = 0; q < 4; q++) c[i][j][q] = 0.f;

    // Precomputed ldmatrix lane addressing offsets (bytes, within a tile)
    // A frag (m16k16): rows wm*32+mf*16 + ((lane>>3)&1)*8 + (lane&7),
    //                  k = ks + (lane>>4)*8
    const uint32_t a_row = (uint32_t)(wm * 32 + ((lane >> 3) & 1) * 8 + (lane & 7));
    const uint32_t a_kof = (uint32_t)((lane >> 4) * 8);
    // B frags (2 per x4): n = wn*64 + nq*16 + (lane>>4)*8 + (lane&7),
    //                  k = ks + ((lane>>3)&1)*8
    const uint32_t b_row = (uint32_t)(wn * 64 + (lane >> 4) * 8 + (lane & 7));
    const uint32_t b_kof = (uint32_t)(((lane >> 3) & 1) * 8);

    load_stage(sb0, Ahi, Alo, Bhi, Blo, m0, n0, 0, tid);
    CP_COMMIT();

#pragma unroll 1
    for (int t = 0; t < DM / KC; t++) {
        if (t + 1 < DM / KC) {
            load_stage(sb0 + ((t + 1) & 1) * STAGE_B, Ahi, Alo, Bhi, Blo,
                       m0, n0, (t + 1) * KC, tid);
            CP_COMMIT();
            CP_WAIT(1);
        } else {
            CP_WAIT(0);
        }
        __syncthreads();

        const uint32_t st = sb0 + (t & 1) * STAGE_B;
#pragma unroll
        for (int ks = 0; ks < 2; ks++) {
            const uint32_t k0 = (uint32_t)(ks * 16);
            uint32_t ah[8], al[8], bh[16], bl[16];
#pragma unroll
            for (int mf = 0; mf < 2; mf++) {
                uint32_t ad = st + (a_row + mf * 16) * ROWB + (k0 + a_kof) * 2;
                LDSM_X4(&ah[4 * mf], ad);
                LDSM_X4(&al[4 * mf], ad + TILE_B);
            }
#pragma unroll
            for (int nq = 0; nq < 4; nq++) {
                uint32_t bd = st + 2 * TILE_B + (b_row + nq * 16) * ROWB
                            + (k0 + b_kof) * 2;
                LDSM_X4(&bh[4 * nq], bd);
                LDSM_X4(&bl[4 * nq], bd + TILE_B);
            }
            // hi*hi
#pragma unroll
            for (int mf = 0; mf < 2; mf++)
#pragma unroll
                for (int nf = 0; nf < 8; nf++)
                    MMA_BF16(c[mf][nf], &ah[4 * mf], &bh[2 * nf]);
            // hi*lo
#pragma unroll
            for (int mf = 0; mf < 2; mf++)
#pragma unroll
                for (int nf = 0; nf < 8; nf++)
                    MMA_BF16(c[mf][nf], &ah[4 * mf], &bl[2 * nf]);
            // lo*hi
#pragma unroll
            for (int mf = 0; mf < 2; mf++)
#pragma unroll
                for (int nf = 0; nf < 8; nf++)
                    MMA_BF16(c[mf][nf], &al[4 * mf], &bh[2 * nf]);
        }
        __syncthreads();
    }

    // Epilogue: C frag thread mapping: {c0,c1} at (row=lane>>2, col=2*(lane&3)),
    // {c2,c3} at (row+8, col). Warp covers rows wm*32..+31, cols wn*64..+63.
    const int rb0 = m0 + wm * 32 + (lane >> 2);
    const int cb  = 2 * (lane & 3);

    if (mode == 0) {
        const int sel = n0 >> 10;
        const int nl  = (n0 & 1023) + wn * 64;   // head-aligned (64)
        const int h   = nl >> 6;
        float* dst = (sel == 0) ? g_q : (sel == 1) ? g_k : g_v;
        const float* bias = ((sel == 0) ? bias0 : (sel == 1) ? bias1 : bias2)
                          + h * DH;
        const int b  = rb0 >> 11;                // tile never crosses batch
        const int s0 = rb0 & (SS - 1);
        float* basep = dst + ((size_t)(b * NH + h) * SS) * DH;
#pragma unroll
        for (int mf = 0; mf < 2; mf++) {
#pragma unroll
            for (int nf = 0; nf < 8; nf++) {
                int d = nf * 8 + cb;
                float bx = bias[d], by = bias[d + 1];
                float2 v0 = make_float2(c[mf][nf][0] + bx, c[mf][nf][1] + by);
                float2 v1 = make_float2(c[mf][nf][2] + bx, c[mf][nf][3] + by);
                *(float2*)(basep + (size_t)(s0 + mf * 16) * DH + d)     = v0;
                *(float2*)(basep + (size_t)(s0 + mf * 16 + 8) * DH + d) = v1;
            }
        }
    } else {
        const int nb = n0 + wn * 64;
        const float* bias = bias0 + nb;
        float* op = outp + (size_t)rb0 * DM + nb;
#pragma unroll
        for (int mf = 0; mf < 2; mf++) {
#pragma unroll
            for (int nf = 0; nf < 8; nf++) {
                int d = nf * 8 + cb;
                float bx = bias[d], by = bias[d + 1];
                float2 v0 = make_float2(c[mf][nf][0] + bx, c[mf][nf][1] + by);
                float2 v1 = make_float2(c[mf][nf][2] + bx, c[mf][nf][3] + by);
                *(float2*)(op + (size_t)(mf * 16) * DM + d)       = v0;
                *(float2*)(op + (size_t)(mf * 16 + 8) * DM + d)   = v1;
            }
        }
    }
}

// ---------------------------------------------------------------------------
// Causal flash attention, fp32 (unchanged — Round 4 target)
// ---------------------------------------------------------------------------
__global__ void __launch_bounds__(128) attn_kernel()
{
    __shared__ float sK[32][64];
    __shared__ float sV[32][64];
    __shared__ float sS[128][33];

    const int tid = threadIdx.x;
    const int bh  = blockIdx.y;
    const int qb  = (int)gridDim.x - 1 - (int)blockIdx.x;
    const int row = qb * 128 + tid;

    const float* Q = g_q + (size_t)bh * SS * DH;
    const float* K = g_k + (size_t)bh * SS * DH;
    const float* V = g_v + (size_t)bh * SS * DH;

    float2 q2[32];
    {
        const float4* qrow = (const float4*)(Q + (size_t)row * DH);
#pragma unroll
        for (int i = 0; i < 16; i++) {
            float4 t = qrow[i];
            q2[2 * i]     = make_float2(t.x, t.y);
            q2[2 * i + 1] = make_float2(t.z, t.w);
        }
    }
    float2 o2[32];
#pragma unroll
    for (int i = 0; i < 32; i++) o2[i] = make_float2(0.f, 0.f);
    float m = __int_as_float(0xff800000);
    float l = 0.f;

    const int ntiles = qb * 4 + 4;
    for (int t = 0; t < ntiles; t++) {
        const int j0 = t * 32;
#pragma unroll
        for (int i = 0; i < 4; i++) {
            int l4 = tid + i * 128;
            int r  = l4 >> 4;
            int cc = (l4 & 15) * 4;
            *(float4*)&sK[r][cc] = *(const float4*)(K + (size_t)(j0 + r) * DH + cc);
            *(float4*)&sV[r][cc] = *(const float4*)(V + (size_t)(j0 + r) * DH + cc);
        }
        __syncthreads();

        int jmax = row - j0 + 1;
        if (jmax > 32) jmax = 32;
        if (jmax > 0) {
            float tmax = __int_as_float(0xff800000);
            for (int j = 0; j < jmax; j++) {
                const float2* kr = (const float2*)&sK[j][0];
                float2 a0 = make_float2(0.f, 0.f), a1 = a0, a2 = a0, a3 = a0;
#pragma unroll
                for (int i = 0; i < 32; i += 4) {
                    ffma2(a0, q2[i],     kr[i]);
                    ffma2(a1, q2[i + 1], kr[i + 1]);
                    ffma2(a2, q2[i + 2], kr[i + 2]);
                    ffma2(a3, q2[i + 3], kr[i + 3]);
                }
                float s = ((a0.x + a0.y) + (a1.x + a1.y)) +
                          ((a2.x + a2.y) + (a3.x + a3.y));
                s *= 0.125f;
                sS[tid][j] = s;
                tmax = fmaxf(tmax, s);
            }
            float mnew = fmaxf(m, tmax);
            float corr = __expf(m - mnew);
            m = mnew;
            l *= corr;
            float2 cc2 = make_float2(corr, corr);
#pragma unroll
            for (int i = 0; i < 32; i++) fmul2(o2[i], cc2);
            for (int j = 0; j < jmax; j++) {
                float p = __expf(sS[tid][j] - m);
                l += p;
                float2 p2 = make_float2(p, p);
                const float2* vr = (const float2*)&sV[j][0];
#pragma unroll
                for (int i = 0; i < 32; i++) ffma2(o2[i], p2, vr[i]);
            }
        }
        __syncthreads();
    }

    const float invl = 1.0f / l;
    const int b = bh >> 4, h = bh & 15;
    float* zrow = g_z + ((size_t)(b * SS + row) * NH + h) * DH;
#pragma unroll
    for (int i = 0; i < 16; i++) {
        float4 tvec;
        tvec.x = o2[2 * i].x * invl;
        tvec.y = o2[2 * i].y * invl;
        tvec.z = o2[2 * i + 1].x * invl;
        tvec.w = o2[2 * i + 1].y * invl;
        *(float4*)(zrow + i * 4) = tvec;
    }
}

// ---------------------------------------------------------------------------
// Launch sequence
// ---------------------------------------------------------------------------
extern "C" void kernel_launch(void* const* d_in, const int* in_sizes, int n_in,
                              void* d_out, int out_size)
{
    (void)in_sizes; (void)n_in; (void)out_size;
    const float* resid = (const float*)d_in[0];
    const float* Wq    = (const float*)d_in[1];
    const float* Wk    = (const float*)d_in[2];
    const float* Wv    = (const float*)d_in[3];
    const float* Wo    = (const float*)d_in[4];
    const float* bq    = (const float*)d_in[5];
    const float* bk    = (const float*)d_in[6];
    const float* bv    = (const float*)d_in[7];
    const float* bo    = (const float*)d_in[8];
    float* out = (float*)d_out;

    cudaFuncSetAttribute(mma_gemm_kernel,
                         cudaFuncAttributeMaxDynamicSharedMemorySize, SMEM_DYN);

    // fp32 -> bf16 hi/lo conversions
    split_x_kernel<<<(MR * DM / 4) / 256, 256>>>(resid);
    conv_wqkv_kernel<<<(3072 * 256) / 256, 256>>>(Wq, Wk, Wv);
    conv_wo_kernel<<<(1024 * 256) / 256, 256>>>(Wo);

    // QKV projection (tensor cores, mma.sync bf16 x3)
    mma_gemm_kernel<<<dim3(24, 64), 256, SMEM_DYN>>>(bq, bk, bv, nullptr, 0);

    // attention (fp32)
    attn_kernel<<<dim3(16, 64), 128>>>();

    // z -> bf16 hi/lo, then output projection
    split_z_kernel<<<(MR * DM / 4) / 256, 256>>>();
    mma_gemm_kernel<<<dim3(8, 64), 256, SMEM_DYN>>>(bo, bo, bo, out, 1);
}

// round 4
// speedup vs baseline: 3.0772x; 1.9913x over previous
#include <cuda_runtime.h>
#include <cuda_bf16.h>
#include <cstdint>

// Problem constants
#define DM 1024      // d_model
#define NH 16        // n_heads
#define DH 64        // d_head
#define BB 4         // batch
#define SS 2048      // seq len
#define MR (BB*SS)   // 8192 rows

// ---------------------------------------------------------------------------
// Scratch (static device globals) — everything bf16 hi/lo now
// q,k,v: [b][h][s][d]; z: [b][s][h][d] == [8192][1024]
// ---------------------------------------------------------------------------
static __device__ __nv_bfloat16 g_qhi[(size_t)BB * NH * SS * DH];
static __device__ __nv_bfloat16 g_qlo[(size_t)BB * NH * SS * DH];
static __device__ __nv_bfloat16 g_khi[(size_t)BB * NH * SS * DH];
static __device__ __nv_bfloat16 g_klo[(size_t)BB * NH * SS * DH];
static __device__ __nv_bfloat16 g_vhi[(size_t)BB * NH * SS * DH];
static __device__ __nv_bfloat16 g_vlo[(size_t)BB * NH * SS * DH];
static __device__ __nv_bfloat16 g_zhi[(size_t)MR * DM];
static __device__ __nv_bfloat16 g_zlo[(size_t)MR * DM];

static __device__ __nv_bfloat16 g_xhi[(size_t)MR * DM];
static __device__ __nv_bfloat16 g_xlo[(size_t)MR * DM];
static __device__ __nv_bfloat16 g_wthi[(size_t)3 * DM * DM];  // [3072][1024], B[n][k]
static __device__ __nv_bfloat16 g_wtlo[(size_t)3 * DM * DM];
static __device__ __nv_bfloat16 g_wohi[(size_t)DM * DM];      // [1024][1024], B[n][k]
static __device__ __nv_bfloat16 g_wolo[(size_t)DM * DM];

// ---------------------------------------------------------------------------
// Base-arch PTX helpers (compute_103 base: no tcgen05; mma.sync/ldmatrix/
// cp.async are fine)
// ---------------------------------------------------------------------------
__device__ __forceinline__ uint32_t smem_to_u32(const void* p) {
    uint32_t a;
    asm("{ .reg .u64 t; cvta.to.shared.u64 t, %1; cvt.u32.u64 %0, t; }"
        : "=r"(a) : "l"(p));
    return a;
}

#define CP_ASYNC16(saddr, gptr) \
    asm volatile("cp.async.cg.shared.global [%0], [%1], 16;" \
        :: "r"(saddr), "l"(gptr))
#define CP_COMMIT() asm volatile("cp.async.commit_group;" ::: "memory")
#define CP_WAIT(n)  asm volatile("cp.async.wait_group %0;" :: "n"(n) : "memory")

#define LDSM_X4(r, addr) \
    asm volatile("ldmatrix.sync.aligned.m8n8.x4.shared.b16 {%0,%1,%2,%3}, [%4];" \
        : "=r"((r)[0]), "=r"((r)[1]), "=r"((r)[2]), "=r"((r)[3]) : "r"(addr))

#define LDSM_X4_T(r, addr) \
    asm volatile("ldmatrix.sync.aligned.m8n8.x4.trans.shared.b16 {%0,%1,%2,%3}, [%4];" \
        : "=r"((r)[0]), "=r"((r)[1]), "=r"((r)[2]), "=r"((r)[3]) : "r"(addr))

#define MMA_BF16(c, a, b) \
    asm volatile("mma.sync.aligned.m16n8k16.row.col.f32.bf16.bf16.f32 " \
        "{%0,%1,%2,%3}, {%4,%5,%6,%7}, {%8,%9}, {%0,%1,%2,%3};" \
        : "+f"((c)[0]), "+f"((c)[1]), "+f"((c)[2]), "+f"((c)[3]) \
        : "r"((a)[0]), "r"((a)[1]), "r"((a)[2]), "r"((a)[3]), \
          "r"((b)[0]), "r"((b)[1]))

// ---------------------------------------------------------------------------
// fp32 -> bf16 hi/lo split helpers
// ---------------------------------------------------------------------------
__device__ __forceinline__ void splitbf(float x, __nv_bfloat16 &h, __nv_bfloat16 &l) {
    h = __float2bfloat16(x);
    l = __float2bfloat16(x - __bfloat162float(h));
}

__device__ __forceinline__ void split2u(float x, float y, uint32_t &h32, uint32_t &l32) {
    __nv_bfloat16 hx, hy, lx, ly;
    splitbf(x, hx, lx);
    splitbf(y, hy, ly);
    __nv_bfloat162 th, tl;
    th.x = hx; th.y = hy;
    tl.x = lx; tl.y = ly;
    h32 = *(uint32_t*)&th;
    l32 = *(uint32_t*)&tl;
}

__device__ __forceinline__ void split4_store(float4 v, __nv_bfloat16* hi,
                                             __nv_bfloat16* lo, size_t i4) {
    uint32_t h0, l0, h1, l1;
    split2u(v.x, v.y, h0, l0);
    split2u(v.z, v.w, h1, l1);
    uint32_t* H = (uint32_t*)hi;
    uint32_t* L = (uint32_t*)lo;
    H[2 * i4] = h0; H[2 * i4 + 1] = h1;
    L[2 * i4] = l0; L[2 * i4 + 1] = l1;
}

__global__ void __launch_bounds__(256) split_x_kernel(const float* __restrict__ src) {
    size_t i = (size_t)blockIdx.x * 256 + threadIdx.x;   // over MR*DM/4
    float4 v = ((const float4*)src)[i];
    split4_store(v, g_xhi, g_xlo, i);
}

// W_Q/W_K/W_V [h][m][d] -> B[n][k] with n = sel*1024 + h*64 + d, k = m
__global__ void __launch_bounds__(256) conv_wqkv_kernel(
    const float* __restrict__ Wq, const float* __restrict__ Wk,
    const float* __restrict__ Wv)
{
    int idx = blockIdx.x * 256 + threadIdx.x;
    int n  = idx % 3072;
    int kb = idx / 3072;
    int sel = n >> 10, nl = n & 1023, h = nl >> 6, d = nl & 63;
    const float* W = (sel == 0) ? Wq : (sel == 1) ? Wk : Wv;
    const float* s = W + ((size_t)h << 16) + (size_t)(kb * 4) * DH + d;
    float x0 = s[0], x1 = s[DH], x2 = s[2 * DH], x3 = s[3 * DH];
    uint32_t h0, l0, h1, l1;
    split2u(x0, x1, h0, l0);
    split2u(x2, x3, h1, l1);
    size_t o = (size_t)n * DM + kb * 4;
    uint32_t* H = (uint32_t*)(g_wthi + o);
    uint32_t* L = (uint32_t*)(g_wtlo + o);
    H[0] = h0; H[1] = h1; L[0] = l0; L[1] = l1;
}

// Wo flat [1024][1024] (row = h*64+d = k) -> B[n][k] = Wo[k][n]
__global__ void __launch_bounds__(256) conv_wo_kernel(const float* __restrict__ Wo) {
    int idx = blockIdx.x * 256 + threadIdx.x;
    int n  = idx & 1023;
    int kb = idx >> 10;
    const float* s = Wo + (size_t)(kb * 4) * DM + n;
    float x0 = s[0], x1 = s[DM], x2 = s[2 * DM], x3 = s[3 * DM];
    uint32_t h0, l0, h1, l1;
    split2u(x0, x1, h0, l0);
    split2u(x2, x3, h1, l1);
    size_t o = (size_t)n * DM + kb * 4;
    uint32_t* H = (uint32_t*)(g_wohi + o);
    uint32_t* L = (uint32_t*)(g_wolo + o);
    H[0] = h0; H[1] = h1; L[0] = l0; L[1] = l1;
}

// ---------------------------------------------------------------------------
// mma.sync bf16 GEMM (3-term split). CTA 128x128, 8 warps, K-chunk 32,
// double-buffered cp.async.
// mode 0: A=X, B=Wqkv^T; epilogue splits to g_{q,k,v}{hi,lo} + bias
// mode 1: A=Z(hi/lo), B=Wo^T; writes fp32 out + bO (bias0)
// ---------------------------------------------------------------------------
#define KC 32
#define PADE 40
#define ROWB (PADE*2)
#define TILE_B (128*ROWB)
#define STAGE_B (4*TILE_B)
#define SMEM_DYN (2*STAGE_B)

__device__ __forceinline__ void load_stage(uint32_t sb,
    const __nv_bfloat16* Ah, const __nv_bfloat16* Al,
    const __nv_bfloat16* Bh, const __nv_bfloat16* Bl,
    int m0, int n0, int k0, int tid)
{
#pragma unroll
    for (int i = 0; i < 2; i++) {
        int c   = tid + i * 256;
        int row = c >> 2;
        int ko  = (c & 3) * 8;
        uint32_t soff = (uint32_t)(row * ROWB + (c & 3) * 16);
        CP_ASYNC16(sb + 0 * TILE_B + soff, Ah + (size_t)(m0 + row) * DM + k0 + ko);
        CP_ASYNC16(sb + 1 * TILE_B + soff, Al + (size_t)(m0 + row) * DM + k0 + ko);
        CP_ASYNC16(sb + 2 * TILE_B + soff, Bh + (size_t)(n0 + row) * DM + k0 + ko);
        CP_ASYNC16(sb + 3 * TILE_B + soff, Bl + (size_t)(n0 + row) * DM + k0 + ko);
    }
}

__global__ void __launch_bounds__(256) mma_gemm_kernel(
    const float* __restrict__ bias0, const float* __restrict__ bias1,
    const float* __restrict__ bias2, float* __restrict__ outp, int mode)
{
    extern __shared__ char smem[];
    const uint32_t sb0 = smem_to_u32(smem);

    const int tid  = threadIdx.x;
    const int lane = tid & 31;
    const int wid  = tid >> 5;
    const int wm   = wid & 3;
    const int wn   = wid >> 2;
    const int m0   = blockIdx.y * 128;
    const int n0   = blockIdx.x * 128;

    const __nv_bfloat16* Ahi = (mode == 0) ? g_xhi  : g_zhi;
    const __nv_bfloat16* Alo = (mode == 0) ? g_xlo  : g_zlo;
    const __nv_bfloat16* Bhi = (mode == 0) ? g_wthi : g_wohi;
    const __nv_bfloat16* Blo = (mode == 0) ? g_wtlo : g_wolo;

    float c[2][8][4];
#pragma unroll
    for (int i = 0; i < 2; i++)
#pragma unroll
        for (int j = 0; j < 8; j++)
#pragma unroll
            for (int q = 0; q < 4; q++) c[i][j][q] = 0.f;

    const uint32_t a_row = (uint32_t)(wm * 32 + ((lane >> 3) & 1) * 8 + (lane & 7));
    const uint32_t a_kof = (uint32_t)((lane >> 4) * 8);
    const uint32_t b_row = (uint32_t)(wn * 64 + (lane >> 4) * 8 + (lane & 7));
    const uint32_t b_kof = (uint32_t)(((lane >> 3) & 1) * 8);

    load_stage(sb0, Ahi, Alo, Bhi, Blo, m0, n0, 0, tid);
    CP_COMMIT();

#pragma unroll 1
    for (int t = 0; t < DM / KC; t++) {
        if (t + 1 < DM / KC) {
            load_stage(sb0 + ((t + 1) & 1) * STAGE_B, Ahi, Alo, Bhi, Blo,
                       m0, n0, (t + 1) * KC, tid);
            CP_COMMIT();
            CP_WAIT(1);
        } else {
            CP_WAIT(0);
        }
        __syncthreads();

        const uint32_t st = sb0 + (t & 1) * STAGE_B;
#pragma unroll
        for (int ks = 0; ks < 2; ks++) {
            const uint32_t k0 = (uint32_t)(ks * 16);
            uint32_t ah[8], al[8], bh[16], bl[16];
#pragma unroll
            for (int mf = 0; mf < 2; mf++) {
                uint32_t ad = st + (a_row + mf * 16) * ROWB + (k0 + a_kof) * 2;
                LDSM_X4(&ah[4 * mf], ad);
                LDSM_X4(&al[4 * mf], ad + TILE_B);
            }
#pragma unroll
            for (int nq = 0; nq < 4; nq++) {
                uint32_t bd = st + 2 * TILE_B + (b_row + nq * 16) * ROWB
                            + (k0 + b_kof) * 2;
                LDSM_X4(&bh[4 * nq], bd);
                LDSM_X4(&bl[4 * nq], bd + TILE_B);
            }
#pragma unroll
            for (int mf = 0; mf < 2; mf++)
#pragma unroll
                for (int nf = 0; nf < 8; nf++)
                    MMA_BF16(c[mf][nf], &ah[4 * mf], &bh[2 * nf]);
#pragma unroll
            for (int mf = 0; mf < 2; mf++)
#pragma unroll
                for (int nf = 0; nf < 8; nf++)
                    MMA_BF16(c[mf][nf], &ah[4 * mf], &bl[2 * nf]);
#pragma unroll
            for (int mf = 0; mf < 2; mf++)
#pragma unroll
                for (int nf = 0; nf < 8; nf++)
                    MMA_BF16(c[mf][nf], &al[4 * mf], &bh[2 * nf]);
        }
        __syncthreads();
    }

    const int rb0 = m0 + wm * 32 + (lane >> 2);
    const int cb  = 2 * (lane & 3);

    if (mode == 0) {
        const int sel = n0 >> 10;
        const int nl  = (n0 & 1023) + wn * 64;
        const int h   = nl >> 6;
        __nv_bfloat16* dsth = (sel == 0) ? g_qhi : (sel == 1) ? g_khi : g_vhi;
        __nv_bfloat16* dstl = (sel == 0) ? g_qlo : (sel == 1) ? g_klo : g_vlo;
        const float* bias = ((sel == 0) ? bias0 : (sel == 1) ? bias1 : bias2)
                          + h * DH;
        const int b  = rb0 >> 11;
        const int s0 = rb0 & (SS - 1);
        size_t base = ((size_t)(b * NH + h) * SS) * DH;
#pragma unroll
        for (int mf = 0; mf < 2; mf++) {
#pragma unroll
            for (int nf = 0; nf < 8; nf++) {
                int d = nf * 8 + cb;
                float bx = bias[d], by = bias[d + 1];
                uint32_t h0, l0, h1, l1;
                split2u(c[mf][nf][0] + bx, c[mf][nf][1] + by, h0, l0);
                split2u(c[mf][nf][2] + bx, c[mf][nf][3] + by, h1, l1);
                size_t i0 = base + (size_t)(s0 + mf * 16) * DH + d;
                size_t i1 = base + (size_t)(s0 + mf * 16 + 8) * DH + d;
                *(uint32_t*)(dsth + i0) = h0;
                *(uint32_t*)(dstl + i0) = l0;
                *(uint32_t*)(dsth + i1) = h1;
                *(uint32_t*)(dstl + i1) = l1;
            }
        }
    } else {
        const int nb = n0 + wn * 64;
        const float* bias = bias0 + nb;
        float* op = outp + (size_t)rb0 * DM + nb;
#pragma unroll
        for (int mf = 0; mf < 2; mf++) {
#pragma unroll
            for (int nf = 0; nf < 8; nf++) {
                int d = nf * 8 + cb;
                float bx = bias[d], by = bias[d + 1];
                float2 v0 = make_float2(c[mf][nf][0] + bx, c[mf][nf][1] + by);
                float2 v1 = make_float2(c[mf][nf][2] + bx, c[mf][nf][3] + by);
                *(float2*)(op + (size_t)(mf * 16) * DM + d)     = v0;
                *(float2*)(op + (size_t)(mf * 16 + 8) * DM + d) = v1;
            }
        }
    }
}

// ---------------------------------------------------------------------------
// Causal flash attention on tensor cores (mma.sync bf16, 3-term split).
// CTA: 128 q-rows x (b,h). 8 warps x 16 q-rows. KV tiles of 64,
// double-buffered cp.async. Online softmax in fp32 registers.
// ---------------------------------------------------------------------------
#define ADHP 72                        // padded row elems (144 B)
#define AROWB (ADHP*2)
#define ATILE (64*AROWB)               // 9216 B per array
#define AOFF_KHI 0
#define AOFF_KLO (ATILE)
#define AOFF_VHI (2*ATILE)
#define AOFF_VLO (3*ATILE)
#define ASTAGE (4*ATILE)               // 36864
#define ASMEM (2*ASTAGE)               // 73728

__device__ __forceinline__ void attn_load(uint32_t sbase,
    const __nv_bfloat16* Kh, const __nv_bfloat16* Kl,
    const __nv_bfloat16* Vh, const __nv_bfloat16* Vl,
    int j0, int tid)
{
#pragma unroll
    for (int i = 0; i < 2; i++) {
        int c   = tid + i * 256;         // 512 chunks of 16B per array
        int row = c >> 3;
        int co  = (c & 7) * 8;           // elem offset
        uint32_t soff = (uint32_t)(row * AROWB + co * 2);
        size_t goff = (size_t)(j0 + row) * DH + co;
        CP_ASYNC16(sbase + AOFF_KHI + soff, Kh + goff);
        CP_ASYNC16(sbase + AOFF_KLO + soff, Kl + goff);
        CP_ASYNC16(sbase + AOFF_VHI + soff, Vh + goff);
        CP_ASYNC16(sbase + AOFF_VLO + soff, Vl + goff);
    }
}

__global__ void __launch_bounds__(256, 1) attn_mma_kernel()
{
    extern __shared__ char smem[];
    const uint32_t sb0 = smem_to_u32(smem);

    const int tid  = threadIdx.x;
    const int lane = tid & 31;
    const int wq   = tid >> 5;                        // 0..7
    const int bh   = blockIdx.y;
    const int qb   = (int)gridDim.x - 1 - (int)blockIdx.x;
    const int q0   = qb * 128;
    const int wr0  = q0 + wq * 16;                    // warp's first q row

    const size_t hb = (size_t)bh * SS * DH;
    const __nv_bfloat16* Kh = g_khi + hb;
    const __nv_bfloat16* Kl = g_klo + hb;
    const __nv_bfloat16* Vh = g_vhi + hb;
    const __nv_bfloat16* Vl = g_vlo + hb;

    // Q A-fragments (held for the whole CTA lifetime)
    const int r0g = wr0 + (lane >> 2);
    const int r1g = r0g + 8;
    uint32_t qh[16], ql[16];
    {
        const __nv_bfloat16* Qh = g_qhi + hb;
        const __nv_bfloat16* Ql = g_qlo + hb;
        const int kb = 2 * (lane & 3);
#pragma unroll
        for (int t = 0; t < 4; t++) {
            int k0 = 16 * t + kb;
            qh[4*t+0] = *(const uint32_t*)(Qh + (size_t)r0g * DH + k0);
            qh[4*t+1] = *(const uint32_t*)(Qh + (size_t)r1g * DH + k0);
            qh[4*t+2] = *(const uint32_t*)(Qh + (size_t)r0g * DH + k0 + 8);
            qh[4*t+3] = *(const uint32_t*)(Qh + (size_t)r1g * DH + k0 + 8);
            ql[4*t+0] = *(const uint32_t*)(Ql + (size_t)r0g * DH + k0);
            ql[4*t+1] = *(const uint32_t*)(Ql + (size_t)r1g * DH + k0);
            ql[4*t+2] = *(const uint32_t*)(Ql + (size_t)r0g * DH + k0 + 8);
            ql[4*t+3] = *(const uint32_t*)(Ql + (size_t)r1g * DH + k0 + 8);
        }
    }

    float o[8][4];
#pragma unroll
    for (int i = 0; i < 8; i++)
#pragma unroll
        for (int j = 0; j < 4; j++) o[i][j] = 0.f;
    float m0 = -1e30f, m1 = -1e30f, l0 = 0.f, l1 = 0.f;

    // ldmatrix per-lane address components
    const int kgrp = lane >> 3, kln = lane & 7;
    const uint32_t krow = (uint32_t)((kgrp >> 1) * 8 + kln);   // K tiles
    const uint32_t kcol = (uint32_t)((kgrp & 1) * 8);
    const uint32_t vrow = (uint32_t)((kgrp & 1) * 8 + kln);    // V tiles (.trans)
    const uint32_t vcol = (uint32_t)((kgrp >> 1) * 8);

    const int ntk = 2 * qb + 2;
    attn_load(sb0, Kh, Kl, Vh, Vl, 0, tid);
    CP_COMMIT();

#pragma unroll 1
    for (int t = 0; t < ntk; t++) {
        if (t + 1 < ntk) {
            attn_load(sb0 + ((t + 1) & 1) * ASTAGE, Kh, Kl, Vh, Vl,
                      (t + 1) * 64, tid);
            CP_COMMIT();
            CP_WAIT(1);
        } else {
            CP_WAIT(0);
        }
        __syncthreads();

        const int kv0 = t * 64;
        if (kv0 <= wr0 + 15) {
            const uint32_t st = sb0 + (t & 1) * ASTAGE;

            // ---- S = Q K^T (split) ----
            float s[8][4];
#pragma unroll
            for (int i = 0; i < 8; i++)
#pragma unroll
                for (int j = 0; j < 4; j++) s[i][j] = 0.f;

#pragma unroll
            for (int dk = 0; dk < 4; dk++) {
#pragma unroll
                for (int ng = 0; ng < 4; ng++) {
                    uint32_t kh4[4], kl4[4];
                    uint32_t ka = st + AOFF_KHI
                                + (uint32_t)(ng * 16 + krow) * AROWB
                                + (uint32_t)(dk * 16 + kcol) * 2;
                    LDSM_X4(kh4, ka);
                    LDSM_X4(kl4, ka + (AOFF_KLO - AOFF_KHI));
                    MMA_BF16(s[2*ng],   &qh[4*dk], &kh4[0]);
                    MMA_BF16(s[2*ng],   &ql[4*dk], &kh4[0]);
                    MMA_BF16(s[2*ng],   &qh[4*dk], &kl4[0]);
                    MMA_BF16(s[2*ng+1], &qh[4*dk], &kh4[2]);
                    MMA_BF16(s[2*ng+1], &ql[4*dk], &kh4[2]);
                    MMA_BF16(s[2*ng+1], &qh[4*dk], &kl4[2]);
                }
            }

            // ---- scale + causal mask ----
            const bool needmask = (kv0 + 63 > wr0);
            const int colb = kv0 + 2 * (lane & 3);
#pragma unroll
            for (int nt = 0; nt < 8; nt++) {
                int c0 = colb + 8 * nt;
#pragma unroll
                for (int e = 0; e < 4; e++) {
                    float v = s[nt][e] * 0.125f;
                    if (needmask) {
                        int col = c0 + (e & 1);
                        int row = (e < 2) ? r0g : r1g;
                        if (col > row) v = -1e30f;
                    }
                    s[nt][e] = v;
                }
            }

            // ---- online softmax ----
            float t0 = -1e30f, t1 = -1e30f;
#pragma unroll
            for (int nt = 0; nt < 8; nt++) {
                t0 = fmaxf(t0, fmaxf(s[nt][0], s[nt][1]));
                t1 = fmaxf(t1, fmaxf(s[nt][2], s[nt][3]));
            }
            t0 = fmaxf(t0, __shfl_xor_sync(0xffffffff, t0, 1));
            t0 = fmaxf(t0, __shfl_xor_sync(0xffffffff, t0, 2));
            t1 = fmaxf(t1, __shfl_xor_sync(0xffffffff, t1, 1));
            t1 = fmaxf(t1, __shfl_xor_sync(0xffffffff, t1, 2));

            float mn0 = fmaxf(m0, t0), mn1 = fmaxf(m1, t1);
            float cr0 = __expf(m0 - mn0), cr1 = __expf(m1 - mn1);
            m0 = mn0; m1 = mn1;

            float ts0 = 0.f, ts1 = 0.f;
#pragma unroll
            for (int nt = 0; nt < 8; nt++) {
                s[nt][0] = __expf(s[nt][0] - m0);
                s[nt][1] = __expf(s[nt][1] - m0);
                s[nt][2] = __expf(s[nt][2] - m1);
                s[nt][3] = __expf(s[nt][3] - m1);
                ts0 += s[nt][0] + s[nt][1];
                ts1 += s[nt][2] + s[nt][3];
            }
            ts0 += __shfl_xor_sync(0xffffffff, ts0, 1);
            ts0 += __shfl_xor_sync(0xffffffff, ts0, 2);
            ts1 += __shfl_xor_sync(0xffffffff, ts1, 1);
            ts1 += __shfl_xor_sync(0xffffffff, ts1, 2);
            l0 = l0 * cr0 + ts0;
            l1 = l1 * cr1 + ts1;

#pragma unroll
            for (int nt = 0; nt < 8; nt++) {
                o[nt][0] *= cr0; o[nt][1] *= cr0;
                o[nt][2] *= cr1; o[nt][3] *= cr1;
            }

            // ---- O += P V (split) ----
#pragma unroll
            for (int tp = 0; tp < 4; tp++) {
                uint32_t ph[4], pl[4];
                split2u(s[2*tp][0],   s[2*tp][1],   ph[0], pl[0]);
                split2u(s[2*tp][2],   s[2*tp][3],   ph[1], pl[1]);
                split2u(s[2*tp+1][0], s[2*tp+1][1], ph[2], pl[2]);
                split2u(s[2*tp+1][2], s[2*tp+1][3], ph[3], pl[3]);
#pragma unroll
                for (int dn2 = 0; dn2 < 4; dn2++) {
                    uint32_t vh4[4], vl4[4];
                    uint32_t va = st + AOFF_VHI
                                + (uint32_t)(tp * 16 + vrow) * AROWB
                                + (uint32_t)(dn2 * 16 + vcol) * 2;
                    LDSM_X4_T(vh4, va);
                    LDSM_X4_T(vl4, va + (AOFF_VLO - AOFF_VHI));
                    MMA_BF16(o[2*dn2],   ph, &vh4[0]);
                    MMA_BF16(o[2*dn2],   pl, &vh4[0]);
                    MMA_BF16(o[2*dn2],   ph, &vl4[0]);
                    MMA_BF16(o[2*dn2+1], ph, &vh4[2]);
                    MMA_BF16(o[2*dn2+1], pl, &vh4[2]);
                    MMA_BF16(o[2*dn2+1], ph, &vl4[2]);
                }
            }
        }
        __syncthreads();
    }

    // ---- normalize, split, store z (bf16 hi/lo, [b][s][h][d]) ----
    const float i0 = 1.f / l0, i1 = 1.f / l1;
    const int b = bh >> 4, h = bh & 15;
    const int cb = 2 * (lane & 3);
#pragma unroll
    for (int nt = 0; nt < 8; nt++) {
        int d = 8 * nt + cb;
        size_t z0 = ((size_t)(b * SS + r0g) * NH + h) * DH + d;
        size_t z1 = ((size_t)(b * SS + r1g) * NH + h) * DH + d;
        uint32_t h32, l32;
        split2u(o[nt][0] * i0, o[nt][1] * i0, h32, l32);
        *(uint32_t*)(g_zhi + z0) = h32;
        *(uint32_t*)(g_zlo + z0) = l32;
        split2u(o[nt][2] * i1, o[nt][3] * i1, h32, l32);
        *(uint32_t*)(g_zhi + z1) = h32;
        *(uint32_t*)(g_zlo + z1) = l32;
    }
}

// ---------------------------------------------------------------------------
// Launch sequence
// ---------------------------------------------------------------------------
extern "C" void kernel_launch(void* const* d_in, const int* in_sizes, int n_in,
                              void* d_out, int out_size)
{
    (void)in_sizes; (void)n_in; (void)out_size;
    const float* resid = (const float*)d_in[0];
    const float* Wq    = (const float*)d_in[1];
    const float* Wk    = (const float*)d_in[2];
    const float* Wv    = (const float*)d_in[3];
    const float* Wo    = (const float*)d_in[4];
    const float* bq    = (const float*)d_in[5];
    const float* bk    = (const float*)d_in[6];
    const float* bv    = (const float*)d_in[7];
    const float* bo    = (const float*)d_in[8];
    float* out = (float*)d_out;

    cudaFuncSetAttribute(mma_gemm_kernel,
                         cudaFuncAttributeMaxDynamicSharedMemorySize, SMEM_DYN);
    cudaFuncSetAttribute(attn_mma_kernel,
                         cudaFuncAttributeMaxDynamicSharedMemorySize, ASMEM);

    split_x_kernel<<<(MR * DM / 4) / 256, 256>>>(resid);
    conv_wqkv_kernel<<<(3072 * 256) / 256, 256>>>(Wq, Wk, Wv);
    conv_wo_kernel<<<(1024 * 256) / 256, 256>>>(Wo);

    // QKV projection -> bf16 hi/lo q,k,v
    mma_gemm_kernel<<<dim3(24, 64), 256, SMEM_DYN>>>(bq, bk, bv, nullptr, 0);

    // attention (tensor cores) -> bf16 hi/lo z
    attn_mma_kernel<<<dim3(16, 64), 256, ASMEM>>>();

    // output projection -> fp32 out
    mma_gemm_kernel<<<dim3(8, 64), 256, SMEM_DYN>>>(bo, bo, bo, out, 1);
}

// round 5
// speedup vs baseline: 3.1934x; 1.0378x over previous
#include <cuda_runtime.h>
#include <cuda_bf16.h>
#include <cstdint>

// Problem constants
#define DM 1024      // d_model
#define NH 16        // n_heads
#define DH 64        // d_head
#define BB 4         // batch
#define SS 2048      // seq len
#define MR (BB*SS)   // 8192 rows

// ---------------------------------------------------------------------------
// Scratch (static device globals) — bf16 hi/lo everywhere
// q,k,v: [b][h][s][d]; z: [b][s][h][d] == [8192][1024]
// ---------------------------------------------------------------------------
static __device__ __nv_bfloat16 g_qhi[(size_t)BB * NH * SS * DH];
static __device__ __nv_bfloat16 g_qlo[(size_t)BB * NH * SS * DH];
static __device__ __nv_bfloat16 g_khi[(size_t)BB * NH * SS * DH];
static __device__ __nv_bfloat16 g_klo[(size_t)BB * NH * SS * DH];
static __device__ __nv_bfloat16 g_vhi[(size_t)BB * NH * SS * DH];
static __device__ __nv_bfloat16 g_vlo[(size_t)BB * NH * SS * DH];
static __device__ __nv_bfloat16 g_zhi[(size_t)MR * DM];
static __device__ __nv_bfloat16 g_zlo[(size_t)MR * DM];

static __device__ __nv_bfloat16 g_xhi[(size_t)MR * DM];
static __device__ __nv_bfloat16 g_xlo[(size_t)MR * DM];
static __device__ __nv_bfloat16 g_wthi[(size_t)3 * DM * DM];  // [3072][1024], B[n][k]
static __device__ __nv_bfloat16 g_wtlo[(size_t)3 * DM * DM];
static __device__ __nv_bfloat16 g_wohi[(size_t)DM * DM];      // [1024][1024], B[n][k]
static __device__ __nv_bfloat16 g_wolo[(size_t)DM * DM];

// ---------------------------------------------------------------------------
// Base-arch PTX helpers (compute_103 base: no tcgen05; mma.sync/ldmatrix/
// cp.async compile fine)
// ---------------------------------------------------------------------------
__device__ __forceinline__ uint32_t smem_to_u32(const void* p) {
    uint32_t a;
    asm("{ .reg .u64 t; cvta.to.shared.u64 t, %1; cvt.u32.u64 %0, t; }"
        : "=r"(a) : "l"(p));
    return a;
}

#define CP_ASYNC16(saddr, gptr) \
    asm volatile("cp.async.cg.shared.global [%0], [%1], 16;" \
        :: "r"(saddr), "l"(gptr))
#define CP_COMMIT() asm volatile("cp.async.commit_group;" ::: "memory")
#define CP_WAIT(n)  asm volatile("cp.async.wait_group %0;" :: "n"(n) : "memory")

#define LDSM_X4(r, addr) \
    asm volatile("ldmatrix.sync.aligned.m8n8.x4.shared.b16 {%0,%1,%2,%3}, [%4];" \
        : "=r"((r)[0]), "=r"((r)[1]), "=r"((r)[2]), "=r"((r)[3]) : "r"(addr))

#define LDSM_X4_T(r, addr) \
    asm volatile("ldmatrix.sync.aligned.m8n8.x4.trans.shared.b16 {%0,%1,%2,%3}, [%4];" \
        : "=r"((r)[0]), "=r"((r)[1]), "=r"((r)[2]), "=r"((r)[3]) : "r"(addr))

#define MMA_BF16(c, a, b) \
    asm volatile("mma.sync.aligned.m16n8k16.row.col.f32.bf16.bf16.f32 " \
        "{%0,%1,%2,%3}, {%4,%5,%6,%7}, {%8,%9}, {%0,%1,%2,%3};" \
        : "+f"((c)[0]), "+f"((c)[1]), "+f"((c)[2]), "+f"((c)[3]) \
        : "r"((a)[0]), "r"((a)[1]), "r"((a)[2]), "r"((a)[3]), \
          "r"((b)[0]), "r"((b)[1]))

// ---------------------------------------------------------------------------
// fp32 -> bf16 hi/lo split helpers
// ---------------------------------------------------------------------------
__device__ __forceinline__ void splitbf(float x, __nv_bfloat16 &h, __nv_bfloat16 &l) {
    h = __float2bfloat16(x);
    l = __float2bfloat16(x - __bfloat162float(h));
}

__device__ __forceinline__ void split2u(float x, float y, uint32_t &h32, uint32_t &l32) {
    __nv_bfloat16 hx, hy, lx, ly;
    splitbf(x, hx, lx);
    splitbf(y, hy, ly);
    __nv_bfloat162 th, tl;
    th.x = hx; th.y = hy;
    tl.x = lx; tl.y = ly;
    h32 = *(uint32_t*)&th;
    l32 = *(uint32_t*)&tl;
}

__device__ __forceinline__ void split4_store(float4 v, __nv_bfloat16* hi,
                                             __nv_bfloat16* lo, size_t i4) {
    uint32_t h0, l0, h1, l1;
    split2u(v.x, v.y, h0, l0);
    split2u(v.z, v.w, h1, l1);
    uint32_t* H = (uint32_t*)hi;
    uint32_t* L = (uint32_t*)lo;
    H[2 * i4] = h0; H[2 * i4 + 1] = h1;
    L[2 * i4] = l0; L[2 * i4 + 1] = l1;
}

__global__ void __launch_bounds__(256) split_x_kernel(const float* __restrict__ src) {
    size_t i = (size_t)blockIdx.x * 256 + threadIdx.x;   // over MR*DM/4
    float4 v = ((const float4*)src)[i];
    split4_store(v, g_xhi, g_xlo, i);
}

// W_Q/W_K/W_V [h][m][d] -> B[n][k] with n = sel*1024 + h*64 + d, k = m
__global__ void __launch_bounds__(256) conv_wqkv_kernel(
    const float* __restrict__ Wq, const float* __restrict__ Wk,
    const float* __restrict__ Wv)
{
    int idx = blockIdx.x * 256 + threadIdx.x;
    int n  = idx % 3072;
    int kb = idx / 3072;
    int sel = n >> 10, nl = n & 1023, h = nl >> 6, d = nl & 63;
    const float* W = (sel == 0) ? Wq : (sel == 1) ? Wk : Wv;
    const float* s = W + ((size_t)h << 16) + (size_t)(kb * 4) * DH + d;
    float x0 = s[0], x1 = s[DH], x2 = s[2 * DH], x3 = s[3 * DH];
    uint32_t h0, l0, h1, l1;
    split2u(x0, x1, h0, l0);
    split2u(x2, x3, h1, l1);
    size_t o = (size_t)n * DM + kb * 4;
    uint32_t* H = (uint32_t*)(g_wthi + o);
    uint32_t* L = (uint32_t*)(g_wtlo + o);
    H[0] = h0; H[1] = h1; L[0] = l0; L[1] = l1;
}

// Wo flat [1024][1024] (row = h*64+d = k) -> B[n][k] = Wo[k][n]
__global__ void __launch_bounds__(256) conv_wo_kernel(const float* __restrict__ Wo) {
    int idx = blockIdx.x * 256 + threadIdx.x;
    int n  = idx & 1023;
    int kb = idx >> 10;
    const float* s = Wo + (size_t)(kb * 4) * DM + n;
    float x0 = s[0], x1 = s[DM], x2 = s[2 * DM], x3 = s[3 * DM];
    uint32_t h0, l0, h1, l1;
    split2u(x0, x1, h0, l0);
    split2u(x2, x3, h1, l1);
    size_t o = (size_t)n * DM + kb * 4;
    uint32_t* H = (uint32_t*)(g_wohi + o);
    uint32_t* L = (uint32_t*)(g_wolo + o);
    H[0] = h0; H[1] = h1; L[0] = l0; L[1] = l1;
}

// ---------------------------------------------------------------------------
// mma.sync bf16 GEMM (3-term split). CTA 128x128, 8 warps, K-chunk 32,
// double-buffered cp.async, SINGLE __syncthreads per k-tile.
// mode 0: A=X, B=Wqkv^T; epilogue splits to g_{q,k,v}{hi,lo} + bias
// mode 1: A=Z(hi/lo), B=Wo^T; writes fp32 out + bO (bias0)
// ---------------------------------------------------------------------------
#define KC 32
#define PADE 40
#define ROWB (PADE*2)
#define TILE_B (128*ROWB)
#define STAGE_B (4*TILE_B)
#define SMEM_DYN (2*STAGE_B)

__device__ __forceinline__ void load_stage(uint32_t sb,
    const __nv_bfloat16* Ah, const __nv_bfloat16* Al,
    const __nv_bfloat16* Bh, const __nv_bfloat16* Bl,
    int m0, int n0, int k0, int tid)
{
#pragma unroll
    for (int i = 0; i < 2; i++) {
        int c   = tid + i * 256;
        int row = c >> 2;
        int ko  = (c & 3) * 8;
        uint32_t soff = (uint32_t)(row * ROWB + (c & 3) * 16);
        CP_ASYNC16(sb + 0 * TILE_B + soff, Ah + (size_t)(m0 + row) * DM + k0 + ko);
        CP_ASYNC16(sb + 1 * TILE_B + soff, Al + (size_t)(m0 + row) * DM + k0 + ko);
        CP_ASYNC16(sb + 2 * TILE_B + soff, Bh + (size_t)(n0 + row) * DM + k0 + ko);
        CP_ASYNC16(sb + 3 * TILE_B + soff, Bl + (size_t)(n0 + row) * DM + k0 + ko);
    }
}

__global__ void __launch_bounds__(256, 2) mma_gemm_kernel(
    const float* __restrict__ bias0, const float* __restrict__ bias1,
    const float* __restrict__ bias2, float* __restrict__ outp, int mode)
{
    extern __shared__ char smem[];
    const uint32_t sb0 = smem_to_u32(smem);

    const int tid  = threadIdx.x;
    const int lane = tid & 31;
    const int wid  = tid >> 5;
    const int wm   = wid & 3;
    const int wn   = wid >> 2;
    const int m0   = blockIdx.y * 128;
    const int n0   = blockIdx.x * 128;

    const __nv_bfloat16* Ahi = (mode == 0) ? g_xhi  : g_zhi;
    const __nv_bfloat16* Alo = (mode == 0) ? g_xlo  : g_zlo;
    const __nv_bfloat16* Bhi = (mode == 0) ? g_wthi : g_wohi;
    const __nv_bfloat16* Blo = (mode == 0) ? g_wtlo : g_wolo;

    float c[2][8][4];
#pragma unroll
    for (int i = 0; i < 2; i++)
#pragma unroll
        for (int j = 0; j < 8; j++)
#pragma unroll
            for (int q = 0; q < 4; q++) c[i][j][q] = 0.f;

    const uint32_t a_row = (uint32_t)(wm * 32 + ((lane >> 3) & 1) * 8 + (lane & 7));
    const uint32_t a_kof = (uint32_t)((lane >> 4) * 8);
    const uint32_t b_row = (uint32_t)(wn * 64 + (lane >> 4) * 8 + (lane & 7));
    const uint32_t b_kof = (uint32_t)(((lane >> 3) & 1) * 8);

    load_stage(sb0, Ahi, Alo, Bhi, Blo, m0, n0, 0, tid);
    CP_COMMIT();

#pragma unroll 1
    for (int t = 0; t < DM / KC; t++) {
        CP_WAIT(0);            // stage t resident (own groups)
        __syncthreads();       // all threads' stage-t data visible; buf t+1 free
        if (t + 1 < DM / KC) { // overlap next-stage loads with compute
            load_stage(sb0 + ((t + 1) & 1) * STAGE_B, Ahi, Alo, Bhi, Blo,
                       m0, n0, (t + 1) * KC, tid);
            CP_COMMIT();
        }

        const uint32_t st = sb0 + (t & 1) * STAGE_B;
#pragma unroll
        for (int ks = 0; ks < 2; ks++) {
            const uint32_t k0 = (uint32_t)(ks * 16);
            uint32_t ah[8], al[8];
#pragma unroll
            for (int mf = 0; mf < 2; mf++) {
                uint32_t ad = st + (a_row + mf * 16) * ROWB + (k0 + a_kof) * 2;
                LDSM_X4(&ah[4 * mf], ad);
                LDSM_X4(&al[4 * mf], ad + TILE_B);
            }
#pragma unroll
            for (int nq = 0; nq < 4; nq++) {
                uint32_t bh4[4], bl4[4];
                uint32_t bd = st + 2 * TILE_B + (b_row + nq * 16) * ROWB
                            + (k0 + b_kof) * 2;
                LDSM_X4(bh4, bd);
                LDSM_X4(bl4, bd + TILE_B);
#pragma unroll
                for (int mf = 0; mf < 2; mf++) {
                    MMA_BF16(c[mf][2 * nq],     &ah[4 * mf], &bh4[0]);
                    MMA_BF16(c[mf][2 * nq + 1], &ah[4 * mf], &bh4[2]);
                    MMA_BF16(c[mf][2 * nq],     &ah[4 * mf], &bl4[0]);
                    MMA_BF16(c[mf][2 * nq + 1], &ah[4 * mf], &bl4[2]);
                    MMA_BF16(c[mf][2 * nq],     &al[4 * mf], &bh4[0]);
                    MMA_BF16(c[mf][2 * nq + 1], &al[4 * mf], &bh4[2]);
                }
            }
        }
    }

    const int rb0 = m0 + wm * 32 + (lane >> 2);
    const int cb  = 2 * (lane & 3);

    if (mode == 0) {
        const int sel = n0 >> 10;
        const int nl  = (n0 & 1023) + wn * 64;
        const int h   = nl >> 6;
        __nv_bfloat16* dsth = (sel == 0) ? g_qhi : (sel == 1) ? g_khi : g_vhi;
        __nv_bfloat16* dstl = (sel == 0) ? g_qlo : (sel == 1) ? g_klo : g_vlo;
        const float* bias = ((sel == 0) ? bias0 : (sel == 1) ? bias1 : bias2)
                          + h * DH;
        const int b  = rb0 >> 11;
        const int s0 = rb0 & (SS - 1);
        size_t base = ((size_t)(b * NH + h) * SS) * DH;
#pragma unroll
        for (int mf = 0; mf < 2; mf++) {
#pragma unroll
            for (int nf = 0; nf < 8; nf++) {
                int d = nf * 8 + cb;
                float bx = bias[d], by = bias[d + 1];
                uint32_t h0, l0, h1, l1;
                split2u(c[mf][nf][0] + bx, c[mf][nf][1] + by, h0, l0);
                split2u(c[mf][nf][2] + bx, c[mf][nf][3] + by, h1, l1);
                size_t i0 = base + (size_t)(s0 + mf * 16) * DH + d;
                size_t i1 = base + (size_t)(s0 + mf * 16 + 8) * DH + d;
                *(uint32_t*)(dsth + i0) = h0;
                *(uint32_t*)(dstl + i0) = l0;
                *(uint32_t*)(dsth + i1) = h1;
                *(uint32_t*)(dstl + i1) = l1;
            }
        }
    } else {
        const int nb = n0 + wn * 64;
        const float* bias = bias0 + nb;
        float* op = outp + (size_t)rb0 * DM + nb;
#pragma unroll
        for (int mf = 0; mf < 2; mf++) {
#pragma unroll
            for (int nf = 0; nf < 8; nf++) {
                int d = nf * 8 + cb;
                float bx = bias[d], by = bias[d + 1];
                float2 v0 = make_float2(c[mf][nf][0] + bx, c[mf][nf][1] + by);
                float2 v1 = make_float2(c[mf][nf][2] + bx, c[mf][nf][3] + by);
                *(float2*)(op + (size_t)(mf * 16) * DM + d)     = v0;
                *(float2*)(op + (size_t)(mf * 16 + 8) * DM + d) = v1;
            }
        }
    }
}

// ---------------------------------------------------------------------------
// Causal flash attention on tensor cores (mma.sync bf16, 3-term split).
// CTA: 128 q-rows x (b,h). 8 warps x 16 q-rows. KV tiles of 64,
// double-buffered cp.async, SINGLE __syncthreads per tile.
// ---------------------------------------------------------------------------
#define ADHP 72                        // padded row elems (144 B)
#define AROWB (ADHP*2)
#define ATILE (64*AROWB)               // 9216 B per array
#define AOFF_KHI 0
#define AOFF_KLO (ATILE)
#define AOFF_VHI (2*ATILE)
#define AOFF_VLO (3*ATILE)
#define ASTAGE (4*ATILE)               // 36864
#define ASMEM (2*ASTAGE)               // 73728

__device__ __forceinline__ void attn_load(uint32_t sbase,
    const __nv_bfloat16* Kh, const __nv_bfloat16* Kl,
    const __nv_bfloat16* Vh, const __nv_bfloat16* Vl,
    int j0, int tid)
{
#pragma unroll
    for (int i = 0; i < 2; i++) {
        int c   = tid + i * 256;         // 512 chunks of 16B per array
        int row = c >> 3;
        int co  = (c & 7) * 8;           // elem offset
        uint32_t soff = (uint32_t)(row * AROWB + co * 2);
        size_t goff = (size_t)(j0 + row) * DH + co;
        CP_ASYNC16(sbase + AOFF_KHI + soff, Kh + goff);
        CP_ASYNC16(sbase + AOFF_KLO + soff, Kl + goff);
        CP_ASYNC16(sbase + AOFF_VHI + soff, Vh + goff);
        CP_ASYNC16(sbase + AOFF_VLO + soff, Vl + goff);
    }
}

__global__ void __launch_bounds__(256, 1) attn_mma_kernel()
{
    extern __shared__ char smem[];
    const uint32_t sb0 = smem_to_u32(smem);

    const int tid  = threadIdx.x;
    const int lane = tid & 31;
    const int wq   = tid >> 5;                        // 0..7
    const int bh   = blockIdx.y;
    const int qb   = (int)gridDim.x - 1 - (int)blockIdx.x;
    const int q0   = qb * 128;
    const int wr0  = q0 + wq * 16;                    // warp's first q row

    const size_t hb = (size_t)bh * SS * DH;
    const __nv_bfloat16* Kh = g_khi + hb;
    const __nv_bfloat16* Kl = g_klo + hb;
    const __nv_bfloat16* Vh = g_vhi + hb;
    const __nv_bfloat16* Vl = g_vlo + hb;

    // Q A-fragments (held for the whole CTA lifetime)
    const int r0g = wr0 + (lane >> 2);
    const int r1g = r0g + 8;
    uint32_t qh[16], ql[16];
    {
        const __nv_bfloat16* Qh = g_qhi + hb;
        const __nv_bfloat16* Ql = g_qlo + hb;
        const int kb = 2 * (lane & 3);
#pragma unroll
        for (int t = 0; t < 4; t++) {
            int k0 = 16 * t + kb;
            qh[4*t+0] = *(const uint32_t*)(Qh + (size_t)r0g * DH + k0);
            qh[4*t+1] = *(const uint32_t*)(Qh + (size_t)r1g * DH + k0);
            qh[4*t+2] = *(const uint32_t*)(Qh + (size_t)r0g * DH + k0 + 8);
            qh[4*t+3] = *(const uint32_t*)(Qh + (size_t)r1g * DH + k0 + 8);
            ql[4*t+0] = *(const uint32_t*)(Ql + (size_t)r0g * DH + k0);
            ql[4*t+1] = *(const uint32_t*)(Ql + (size_t)r1g * DH + k0);
            ql[4*t+2] = *(const uint32_t*)(Ql + (size_t)r0g * DH + k0 + 8);
            ql[4*t+3] = *(const uint32_t*)(Ql + (size_t)r1g * DH + k0 + 8);
        }
    }

    float o[8][4];
#pragma unroll
    for (int i = 0; i < 8; i++)
#pragma unroll
        for (int j = 0; j < 4; j++) o[i][j] = 0.f;
    float m0 = -1e30f, m1 = -1e30f, l0 = 0.f, l1 = 0.f;

    // ldmatrix per-lane address components
    const int kgrp = lane >> 3, kln = lane & 7;
    const uint32_t krow = (uint32_t)((kgrp >> 1) * 8 + kln);   // K tiles
    const uint32_t kcol = (uint32_t)((kgrp & 1) * 8);
    const uint32_t vrow = (uint32_t)((kgrp & 1) * 8 + kln);    // V tiles (.trans)
    const uint32_t vcol = (uint32_t)((kgrp >> 1) * 8);

    const int ntk = 2 * qb + 2;
    attn_load(sb0, Kh, Kl, Vh, Vl, 0, tid);
    CP_COMMIT();

#pragma unroll 1
    for (int t = 0; t < ntk; t++) {
        CP_WAIT(0);
        __syncthreads();
        if (t + 1 < ntk) {
            attn_load(sb0 + ((t + 1) & 1) * ASTAGE, Kh, Kl, Vh, Vl,
                      (t + 1) * 64, tid);
            CP_COMMIT();
        }

        const int kv0 = t * 64;
        if (kv0 <= wr0 + 15) {
            const uint32_t st = sb0 + (t & 1) * ASTAGE;

            // ---- S = Q K^T (split) ----
            float s[8][4];
#pragma unroll
            for (int i = 0; i < 8; i++)
#pragma unroll
                for (int j = 0; j < 4; j++) s[i][j] = 0.f;

#pragma unroll
            for (int dk = 0; dk < 4; dk++) {
#pragma unroll
                for (int ng = 0; ng < 4; ng++) {
                    uint32_t kh4[4], kl4[4];
                    uint32_t ka = st + AOFF_KHI
                                + (uint32_t)(ng * 16 + krow) * AROWB
                                + (uint32_t)(dk * 16 + kcol) * 2;
                    LDSM_X4(kh4, ka);
                    LDSM_X4(kl4, ka + (AOFF_KLO - AOFF_KHI));
                    MMA_BF16(s[2*ng],   &qh[4*dk], &kh4[0]);
                    MMA_BF16(s[2*ng],   &ql[4*dk], &kh4[0]);
                    MMA_BF16(s[2*ng],   &qh[4*dk], &kl4[0]);
                    MMA_BF16(s[2*ng+1], &qh[4*dk], &kh4[2]);
                    MMA_BF16(s[2*ng+1], &ql[4*dk], &kh4[2]);
                    MMA_BF16(s[2*ng+1], &qh[4*dk], &kl4[2]);
                }
            }

            // ---- scale + causal mask ----
            const bool needmask = (kv0 + 63 > wr0);
            const int colb = kv0 + 2 * (lane & 3);
#pragma unroll
            for (int nt = 0; nt < 8; nt++) {
                int c0 = colb + 8 * nt;
#pragma unroll
                for (int e = 0; e < 4; e++) {
                    float v = s[nt][e] * 0.125f;
                    if (needmask) {
                        int col = c0 + (e & 1);
                        int row = (e < 2) ? r0g : r1g;
                        if (col > row) v = -1e30f;
                    }
                    s[nt][e] = v;
                }
            }

            // ---- online softmax ----
            float t0 = -1e30f, t1 = -1e30f;
#pragma unroll
            for (int nt = 0; nt < 8; nt++) {
                t0 = fmaxf(t0, fmaxf(s[nt][0], s[nt][1]));
                t1 = fmaxf(t1, fmaxf(s[nt][2], s[nt][3]));
            }
            t0 = fmaxf(t0, __shfl_xor_sync(0xffffffff, t0, 1));
            t0 = fmaxf(t0, __shfl_xor_sync(0xffffffff, t0, 2));
            t1 = fmaxf(t1, __shfl_xor_sync(0xffffffff, t1, 1));
            t1 = fmaxf(t1, __shfl_xor_sync(0xffffffff, t1, 2));

            float mn0 = fmaxf(m0, t0), mn1 = fmaxf(m1, t1);
            float cr0 = __expf(m0 - mn0), cr1 = __expf(m1 - mn1);
            m0 = mn0; m1 = mn1;

            float ts0 = 0.f, ts1 = 0.f;
#pragma unroll
            for (int nt = 0; nt < 8; nt++) {
                s[nt][0] = __expf(s[nt][0] - m0);
                s[nt][1] = __expf(s[nt][1] - m0);
                s[nt][2] = __expf(s[nt][2] - m1);
                s[nt][3] = __expf(s[nt][3] - m1);
                ts0 += s[nt][0] + s[nt][1];
                ts1 += s[nt][2] + s[nt][3];
            }
            ts0 += __shfl_xor_sync(0xffffffff, ts0, 1);
            ts0 += __shfl_xor_sync(0xffffffff, ts0, 2);
            ts1 += __shfl_xor_sync(0xffffffff, ts1, 1);
            ts1 += __shfl_xor_sync(0xffffffff, ts1, 2);
            l0 = l0 * cr0 + ts0;
            l1 = l1 * cr1 + ts1;

#pragma unroll
            for (int nt = 0; nt < 8; nt++) {
                o[nt][0] *= cr0; o[nt][1] *= cr0;
                o[nt][2] *= cr1; o[nt][3] *= cr1;
            }

            // ---- O += P V (split) ----
#pragma unroll
            for (int tp = 0; tp < 4; tp++) {
                uint32_t ph[4], pl[4];
                split2u(s[2*tp][0],   s[2*tp][1],   ph[0], pl[0]);
                split2u(s[2*tp][2],   s[2*tp][3],   ph[1], pl[1]);
                split2u(s[2*tp+1][0], s[2*tp+1][1], ph[2], pl[2]);
                split2u(s[2*tp+1][2], s[2*tp+1][3], ph[3], pl[3]);
#pragma unroll
                for (int dn2 = 0; dn2 < 4; dn2++) {
                    uint32_t vh4[4], vl4[4];
                    uint32_t va = st + AOFF_VHI
                                + (uint32_t)(tp * 16 + vrow) * AROWB
                                + (uint32_t)(dn2 * 16 + vcol) * 2;
                    LDSM_X4_T(vh4, va);
                    LDSM_X4_T(vl4, va + (AOFF_VLO - AOFF_VHI));
                    MMA_BF16(o[2*dn2],   ph, &vh4[0]);
                    MMA_BF16(o[2*dn2],   pl, &vh4[0]);
                    MMA_BF16(o[2*dn2],   ph, &vl4[0]);
                    MMA_BF16(o[2*dn2+1], ph, &vh4[2]);
                    MMA_BF16(o[2*dn2+1], pl, &vh4[2]);
                    MMA_BF16(o[2*dn2+1], ph, &vl4[2]);
                }
            }
        }
    }

    // ---- normalize, split, store z (bf16 hi/lo, [b][s][h][d]) ----
    const float i0 = 1.f / l0, i1 = 1.f / l1;
    const int b = bh >> 4, h = bh & 15;
    const int cb = 2 * (lane & 3);
#pragma unroll
    for (int nt = 0; nt < 8; nt++) {
        int d = 8 * nt + cb;
        size_t z0 = ((size_t)(b * SS + r0g) * NH + h) * DH + d;
        size_t z1 = ((size_t)(b * SS + r1g) * NH + h) * DH + d;
        uint32_t h32, l32;
        split2u(o[nt][0] * i0, o[nt][1] * i0, h32, l32);
        *(uint32_t*)(g_zhi + z0) = h32;
        *(uint32_t*)(g_zlo + z0) = l32;
        split2u(o[nt][2] * i1, o[nt][3] * i1, h32, l32);
        *(uint32_t*)(g_zhi + z1) = h32;
        *(uint32_t*)(g_zlo + z1) = l32;
    }
}

// ---------------------------------------------------------------------------
// Launch sequence
// ---------------------------------------------------------------------------
extern "C" void kernel_launch(void* const* d_in, const int* in_sizes, int n_in,
                              void* d_out, int out_size)
{
    (void)in_sizes; (void)n_in; (void)out_size;
    const float* resid = (const float*)d_in[0];
    const float* Wq    = (const float*)d_in[1];
    const float* Wk    = (const float*)d_in[2];
    const float* Wv    = (const float*)d_in[3];
    const float* Wo    = (const float*)d_in[4];
    const float* bq    = (const float*)d_in[5];
    const float* bk    = (const float*)d_in[6];
    const float* bv    = (const float*)d_in[7];
    const float* bo    = (const float*)d_in[8];
    float* out = (float*)d_out;

    cudaFuncSetAttribute(mma_gemm_kernel,
                         cudaFuncAttributeMaxDynamicSharedMemorySize, SMEM_DYN);
    cudaFuncSetAttribute(attn_mma_kernel,
                         cudaFuncAttributeMaxDynamicSharedMemorySize, ASMEM);

    split_x_kernel<<<(MR * DM / 4) / 256, 256>>>(resid);
    conv_wqkv_kernel<<<(3072 * 256) / 256, 256>>>(Wq, Wk, Wv);
    conv_wo_kernel<<<(1024 * 256) / 256, 256>>>(Wo);

    // QKV projection -> bf16 hi/lo q,k,v
    mma_gemm_kernel<<<dim3(24, 64), 256, SMEM_DYN>>>(bq, bk, bv, nullptr, 0);

    // attention (tensor cores) -> bf16 hi/lo z
    attn_mma_kernel<<<dim3(16, 64), 256, ASMEM>>>();

    // output projection -> fp32 out
    mma_gemm_kernel<<<dim3(8, 64), 256, SMEM_DYN>>>(bo, bo, bo, out, 1);
}